// round 8
// baseline (speedup 1.0000x reference)
#include <cuda_runtime.h>
#include <cuda_bf16.h>
#include <math.h>

#define Bb   64
#define Tt   200
#define Dd   128
#define Mm   50
#define BT   (Bb*Tt)          // 12800
#define NUMQ 1000
#define NC   8                // scan chunks
#define LL   25               // Tt / NC

// ---------------- scratch ----------------
__device__ float g_k[BT*Dd];
__device__ float g_v[BT*Dd];
__device__ float g_w[BT*Mm];
__device__ float g_e[BT*Dd];
__device__ float g_a[BT*Dd];
__device__ float g_read[BT*Dd];
__device__ float g_read2[BT*Dd];
__device__ float g_Wea[Dd*2*Dd];    // [d][o]: o<128 -> e_W^T, o>=128 -> a_W^T
__device__ float g_fWt[2*Dd*Dd];    // [dd(256)][o(128)]
__device__ float g_A[Bb*NC*Mm*Dd];  // chunk affine scale   [b][ci][m][d]
__device__ float g_B[Bb*NC*Mm*Dd];  // chunk affine offset

__device__ __forceinline__ float sigmoidf_(float x){ return 1.f/(1.f+expf(-x)); }

// ---------------- K1: gather k/v, w logits + softmax, + weight transpose ----------------
__global__ __launch_bounds__(256) void k1_gather(
    const int* __restrict__ q, const int* __restrict__ r, const int* __restrict__ pid,
    const float* __restrict__ pid_emb, const float* __restrict__ k_emb,
    const float* __restrict__ v_emb, const float* __restrict__ Mk,
    const float* __restrict__ eW, const float* __restrict__ aW,
    const float* __restrict__ fW)
{
    const int tid  = threadIdx.x;
    const int lane = tid & 31;
    const int wid  = tid >> 5;
    const int row0 = blockIdx.x * 16;

    // strip-mined weight transpose across the whole grid (one elem per thread)
    {
        int gtid = blockIdx.x*256 + tid;
        if (gtid < Dd*Dd){
            int o = gtid / Dd, d = gtid % Dd;
            g_Wea[d*(2*Dd)+o]    = eW[gtid];
            g_Wea[d*(2*Dd)+Dd+o] = aW[gtid];
        } else if (gtid < Dd*Dd + Dd*2*Dd){
            int i = gtid - Dd*Dd;
            int o = i/(2*Dd), dd = i%(2*Dd);
            g_fWt[dd*Dd+o] = fW[i];
        }
    }

    __shared__ float k_s[16][Dd];
    __shared__ float mk_s[Mm][129];
    __shared__ float wl[16][52];

    for (int i=tid; i<Mm*Dd; i+=256) mk_s[i/Dd][i%Dd] = Mk[i];

    for (int i=tid; i<16*Dd; i+=256){
        int rr = i >> 7, d = i & 127;
        int row = row0 + rr;
        int qi = q[row], ri = r[row], pi = pid[row];
        float pe = pid_emb[pi*Dd + d];
        float kk = k_emb[qi*Dd + d] + pe;
        float vv = v_emb[(qi + ri*NUMQ)*Dd + d] + pe;
        k_s[rr][d] = kk;
        g_k[row*Dd + d] = kk;
        g_v[row*Dd + d] = vv;
    }
    __syncthreads();

    for (int p=tid; p<16*Mm; p+=256){
        int rr = p/Mm, m = p - rr*Mm;
        float acc = 0.f;
        #pragma unroll 4
        for (int d=0; d<Dd; d++) acc = fmaf(mk_s[m][d], k_s[rr][d], acc);
        wl[rr][m] = acc;
    }
    __syncthreads();

    #pragma unroll
    for (int s2=0; s2<2; s2++){
        int rr  = wid*2 + s2;
        int row = row0 + rr;
        float l0 = (lane      < Mm) ? wl[rr][lane]      : -1e30f;
        float l1 = (lane + 32 < Mm) ? wl[rr][lane + 32] : -1e30f;
        float mx = fmaxf(l0, l1);
        #pragma unroll
        for (int o=16; o; o>>=1) mx = fmaxf(mx, __shfl_xor_sync(0xffffffffu, mx, o));
        float e0 = (lane      < Mm) ? expf(l0 - mx) : 0.f;
        float e1 = (lane + 32 < Mm) ? expf(l1 - mx) : 0.f;
        float ss = e0 + e1;
        #pragma unroll
        for (int o=16; o; o>>=1) ss += __shfl_xor_sync(0xffffffffu, ss, o);
        float inv = 1.f / ss;
        if (lane      < Mm) g_w[row*Mm + lane]      = e0 * inv;
        if (lane + 32 < Mm) g_w[row*Mm + lane + 32] = e1 * inv;
    }
}

// ---------------- smem-tiled GEMM: e/a (fused), 32-row tiles ----------------
// grid (400, 2): 32 rows x 128 cols. 128 threads, thread tile 4 rows x 8 cols.
__global__ __launch_bounds__(128) void k_ea_gemm(const float* __restrict__ e_b,
                                                 const float* __restrict__ a_b)
{
    const int tid = threadIdx.x;
    const int tx  = tid & 15;          // col group of 8
    const int ty  = tid >> 4;          // row group of 4 (0..7)
    const int row0 = blockIdx.x * 32;
    const int cb   = blockIdx.y;       // 0 -> e, 1 -> a

    __shared__ float act_s[32][40];    // [kk][row], 160B row stride (16B aligned)
    __shared__ float w_s[32][128];

    float acc[4][8];
    #pragma unroll
    for (int i=0;i<4;i++)
        #pragma unroll
        for (int j=0;j<8;j++) acc[i][j]=0.f;

    for (int kc=0; kc<Dd; kc+=32){
        #pragma unroll
        for (int i=0;i<2;i++){
            int lin = tid + i*128;           // 0..255
            int rr  = lin >> 3;              // 0..31
            int kg  = lin & 7;
            float4 v = *reinterpret_cast<const float4*>(&g_v[(row0+rr)*Dd + kc + kg*4]);
            act_s[kg*4+0][rr]=v.x; act_s[kg*4+1][rr]=v.y; act_s[kg*4+2][rr]=v.z; act_s[kg*4+3][rr]=v.w;
        }
        #pragma unroll
        for (int i=0;i<8;i++){
            int lin = tid + i*128;
            int kk  = lin >> 5;
            int c4  = lin & 31;
            *reinterpret_cast<float4*>(&w_s[kk][c4*4]) =
                *reinterpret_cast<const float4*>(&g_Wea[(kc+kk)*(2*Dd) + cb*Dd + c4*4]);
        }
        __syncthreads();

        #pragma unroll 4
        for (int kk=0; kk<32; kk++){
            float4 a0 = *reinterpret_cast<float4*>(&act_s[kk][ty*4]);
            float4 w0 = *reinterpret_cast<float4*>(&w_s[kk][tx*8]);
            float4 w1 = *reinterpret_cast<float4*>(&w_s[kk][tx*8+4]);
            float av[4] = {a0.x,a0.y,a0.z,a0.w};
            float wv[8] = {w0.x,w0.y,w0.z,w0.w,w1.x,w1.y,w1.z,w1.w};
            #pragma unroll
            for (int i=0;i<4;i++)
                #pragma unroll
                for (int j=0;j<8;j++) acc[i][j] = fmaf(av[i], wv[j], acc[i][j]);
        }
        __syncthreads();
    }

    const float* bias = (cb==0) ? e_b : a_b;
    float4 b0 = *reinterpret_cast<const float4*>(&bias[tx*8]);
    float4 b1 = *reinterpret_cast<const float4*>(&bias[tx*8+4]);
    float bb[8] = {b0.x,b0.y,b0.z,b0.w,b1.x,b1.y,b1.z,b1.w};
    float* dst = (cb==0) ? g_e : g_a;
    #pragma unroll
    for (int i=0;i<4;i++){
        int row = row0 + ty*4 + i;
        float o[8];
        if (cb==0){
            #pragma unroll
            for (int j=0;j<8;j++) o[j] = sigmoidf_(acc[i][j] + bb[j]);
        } else {
            #pragma unroll
            for (int j=0;j<8;j++) o[j] = tanhf(acc[i][j] + bb[j]);
        }
        *reinterpret_cast<float4*>(&dst[row*Dd + tx*8])   = make_float4(o[0],o[1],o[2],o[3]);
        *reinterpret_cast<float4*>(&dst[row*Dd + tx*8+4]) = make_float4(o[4],o[5],o[6],o[7]);
    }
}

// ---------------- K2a: affine composition, d-quad + m-quarter split ----------------
// grid (NC, Bb, 4), 256 threads: lane -> d-quad, wg -> mm in {wg, wg+8} (<=2).
__global__ __launch_bounds__(256) void k2a_affine()
{
    const int ci   = blockIdx.x;
    const int b    = blockIdx.y;
    const int mq   = blockIdx.z;
    const int tid  = threadIdx.x;
    const int lane = tid & 31;
    const int wg   = tid >> 5;
    const int t0   = ci * LL;
    const int m0   = (mq < 2) ? mq*13 : 26 + (mq-2)*12;
    const int mc   = (mq < 2) ? 13 : 12;

    __shared__ float w_s[LL][16];
    for (int i=tid; i<LL*mc; i+=256){
        int tt = i / mc, mm = i - tt*mc;
        w_s[tt][mm] = g_w[((size_t)b*Tt + t0 + tt)*Mm + m0 + mm];
    }
    __syncthreads();

    float4 A[2], Bv[2];
    #pragma unroll
    for (int i=0;i<2;i++){ A[i]=make_float4(1.f,1.f,1.f,1.f); Bv[i]=make_float4(0.f,0.f,0.f,0.f); }

    const float4* eb4 = reinterpret_cast<const float4*>(g_e + ((size_t)b*Tt + t0)*Dd);
    const float4* ab4 = reinterpret_cast<const float4*>(g_a + ((size_t)b*Tt + t0)*Dd);

    #pragma unroll 5
    for (int tt=0; tt<LL; tt++){
        float4 ev = eb4[tt*32 + lane];
        float4 av = ab4[tt*32 + lane];
        #pragma unroll
        for (int i=0;i<2;i++){
            int mm = wg + 8*i;
            if (mm < mc){
                float wv = w_s[tt][mm];
                float cx = fmaf(-wv, ev.x, 1.f);
                float cy = fmaf(-wv, ev.y, 1.f);
                float cz = fmaf(-wv, ev.z, 1.f);
                float cw = fmaf(-wv, ev.w, 1.f);
                A[i].x *= cx; A[i].y *= cy; A[i].z *= cz; A[i].w *= cw;
                Bv[i].x = fmaf(cx, Bv[i].x, wv*av.x);
                Bv[i].y = fmaf(cy, Bv[i].y, wv*av.y);
                Bv[i].z = fmaf(cz, Bv[i].z, wv*av.z);
                Bv[i].w = fmaf(cw, Bv[i].w, wv*av.w);
            }
        }
    }

    size_t base = ((size_t)(b*NC + ci)*Mm)*Dd;
    #pragma unroll
    for (int i=0;i<2;i++){
        int mm = wg + 8*i;
        if (mm < mc){
            *reinterpret_cast<float4*>(&g_A[base + (size_t)(m0+mm)*Dd + lane*4]) = A[i];
            *reinterpret_cast<float4*>(&g_B[base + (size_t)(m0+mm)*Dd + lane*4]) = Bv[i];
        }
    }
}

// ---------------- K2b: chunk-start states -> out_Mv at t = 0,25,...,200 ----------------
__global__ __launch_bounds__(256) void k2b_chunkstart(const float* __restrict__ Mv0,
                                                      float* __restrict__ out_Mv)
{
    const int b    = blockIdx.x;
    const int tid  = threadIdx.x;
    const int lane = tid & 31;
    const int wg   = tid >> 5;

    float4 s[7];
    #pragma unroll
    for (int i=0;i<7;i++){
        int m = wg + 8*i;
        s[i] = (m < Mm) ? *reinterpret_cast<const float4*>(&Mv0[m*Dd + lane*4])
                        : make_float4(0.f,0.f,0.f,0.f);
    }
    {
        float* outp = out_Mv + ((size_t)(b*(Tt+1)) * Mm) * Dd;
        #pragma unroll
        for (int i=0;i<7;i++){
            int m = wg + 8*i;
            if (m < Mm) __stcs(reinterpret_cast<float4*>(&outp[(size_t)m*Dd + lane*4]), s[i]);
        }
    }
    for (int ci=0; ci<NC; ci++){
        size_t base = ((size_t)(b*NC + ci)*Mm)*Dd;
        #pragma unroll
        for (int i=0;i<7;i++){
            int m = wg + 8*i;
            if (m < Mm){
                float4 A  = *reinterpret_cast<const float4*>(&g_A[base + (size_t)m*Dd + lane*4]);
                float4 Bv = *reinterpret_cast<const float4*>(&g_B[base + (size_t)m*Dd + lane*4]);
                s[i].x = fmaf(A.x, s[i].x, Bv.x);
                s[i].y = fmaf(A.y, s[i].y, Bv.y);
                s[i].z = fmaf(A.z, s[i].z, Bv.z);
                s[i].w = fmaf(A.w, s[i].w, Bv.w);
            }
        }
        float* outp = out_Mv + ((size_t)(b*(Tt+1) + (ci+1)*LL) * Mm) * Dd;
        #pragma unroll
        for (int i=0;i<7;i++){
            int m = wg + 8*i;
            if (m < Mm) __stcs(reinterpret_cast<float4*>(&outp[(size_t)m*Dd + lane*4]), s[i]);
        }
    }
}

// ---------------- K2c: expand chunks, 256 threads, d-quad STG.128 ----------------
// grid (NC, Bb, 2): mh = m-half. 8 warps: lane -> d-quad, warp wg owns mm in
// {wg, wg+8, wg+16, wg+24} (<=4). mv[4] float4. Phase-reduced read (7/6/6/6).
__global__ __launch_bounds__(256) void k2c_expand(float* __restrict__ out_Mv)
{
    const int ci = blockIdx.x;
    const int b  = blockIdx.y;
    const int mh = blockIdx.z;
    const int tid  = threadIdx.x;
    const int lane = tid & 31;
    const int wg   = tid >> 5;
    const int t0 = ci * LL;
    const int m0 = mh * 25;

    __shared__ float w_s[LL][28];
    __shared__ float part[8][7][Dd];

    for (int i=tid; i<LL*25; i+=256){
        int tt = i / 25, mm = i - tt*25;
        w_s[tt][mm] = g_w[((size_t)b*Tt + t0 + tt)*Mm + m0 + mm];
    }
    __syncthreads();

    float4 mv[4];
    {
        const float* st = out_Mv + ((size_t)(b*(Tt+1) + t0) * Mm) * Dd;
        #pragma unroll
        for (int i=0;i<4;i++){
            int mm = wg + 8*i;
            mv[i] = (mm < 25) ? *reinterpret_cast<const float4*>(&st[(size_t)(m0+mm)*Dd + lane*4])
                              : make_float4(0.f,0.f,0.f,0.f);
        }
    }

    const float4* eb4 = reinterpret_cast<const float4*>(g_e + ((size_t)b*Tt + t0)*Dd);
    const float4* ab4 = reinterpret_cast<const float4*>(g_a + ((size_t)b*Tt + t0)*Dd);
    float*        rb  = ((mh==0) ? g_read : g_read2) + ((size_t)b*Tt + t0)*Dd;

    int pstart = 0;
    #pragma unroll
    for (int ph=0; ph<4; ph++){
        const int nt = (ph==0) ? 7 : 6;
        for (int tt=pstart; tt<pstart+nt; tt++){
            float4 ev = eb4[tt*32 + lane];
            float4 av = ab4[tt*32 + lane];
            float* outp = out_Mv + ((size_t)(b*(Tt+1) + t0 + tt) * Mm) * Dd;
            float4 racc = make_float4(0.f,0.f,0.f,0.f);
            #pragma unroll
            for (int i=0;i<4;i++){
                int mm = wg + 8*i;
                if (mm < 25){
                    float wv = w_s[tt][mm];
                    float4 s = mv[i];
                    racc.x = fmaf(wv, s.x, racc.x);
                    racc.y = fmaf(wv, s.y, racc.y);
                    racc.z = fmaf(wv, s.z, racc.z);
                    racc.w = fmaf(wv, s.w, racc.w);
                    if (tt > 0)
                        __stcs(reinterpret_cast<float4*>(&outp[(size_t)(m0+mm)*Dd + lane*4]), s);
                    float wex = wv * ev.x, wey = wv * ev.y, wez = wv * ev.z, wew = wv * ev.w;
                    mv[i].x = fmaf(wv, av.x, fmaf(-wex, s.x, s.x));
                    mv[i].y = fmaf(wv, av.y, fmaf(-wey, s.y, s.y));
                    mv[i].z = fmaf(wv, av.z, fmaf(-wez, s.z, s.z));
                    mv[i].w = fmaf(wv, av.w, fmaf(-wew, s.w, s.w));
                }
            }
            *reinterpret_cast<float4*>(&part[wg][tt-pstart][lane*4]) = racc;
        }
        __syncthreads();
        for (int idx=tid; idx<nt*32; idx+=256){
            int tt = idx >> 5, l = idx & 31;
            float4 rs = make_float4(0.f,0.f,0.f,0.f);
            #pragma unroll
            for (int j=0;j<8;j++){
                float4 p = *reinterpret_cast<float4*>(&part[j][tt][l*4]);
                rs.x += p.x; rs.y += p.y; rs.z += p.z; rs.w += p.w;
            }
            *reinterpret_cast<float4*>(&rb[(size_t)(pstart+tt)*Dd + l*4]) = rs;
        }
        __syncthreads();
        pstart += nt;
    }
}

// ---------------- smem-tiled GEMM: f + p head, 32-row tiles ----------------
__global__ __launch_bounds__(128) void k_f_gemm(const float* __restrict__ f_b,
                                                const float* __restrict__ p_W,
                                                const float* __restrict__ p_b,
                                                float* __restrict__ out_p)
{
    const int tid = threadIdx.x;
    const int tx  = tid & 15;
    const int ty  = tid >> 4;
    const int row0 = blockIdx.x * 32;

    __shared__ float act_s[32][40];
    __shared__ float w_s[32][128];

    float acc[4][8];
    #pragma unroll
    for (int i=0;i<4;i++)
        #pragma unroll
        for (int j=0;j<8;j++) acc[i][j]=0.f;

    for (int kc=0; kc<2*Dd; kc+=32){
        if (kc < Dd){
            const float* src1 = g_read  + (size_t)row0*Dd + kc;
            const float* src2 = g_read2 + (size_t)row0*Dd + kc;
            #pragma unroll
            for (int i=0;i<2;i++){
                int lin = tid + i*128;
                int rr  = lin >> 3;
                int kg  = lin & 7;
                float4 v1 = *reinterpret_cast<const float4*>(&src1[rr*Dd + kg*4]);
                float4 v2 = *reinterpret_cast<const float4*>(&src2[rr*Dd + kg*4]);
                act_s[kg*4+0][rr]=v1.x+v2.x; act_s[kg*4+1][rr]=v1.y+v2.y;
                act_s[kg*4+2][rr]=v1.z+v2.z; act_s[kg*4+3][rr]=v1.w+v2.w;
            }
        } else {
            const float* src = g_k + (size_t)row0*Dd + (kc - Dd);
            #pragma unroll
            for (int i=0;i<2;i++){
                int lin = tid + i*128;
                int rr  = lin >> 3;
                int kg  = lin & 7;
                float4 v = *reinterpret_cast<const float4*>(&src[rr*Dd + kg*4]);
                act_s[kg*4+0][rr]=v.x; act_s[kg*4+1][rr]=v.y; act_s[kg*4+2][rr]=v.z; act_s[kg*4+3][rr]=v.w;
            }
        }
        #pragma unroll
        for (int i=0;i<8;i++){
            int lin = tid + i*128;
            int kk  = lin >> 5;
            int c4  = lin & 31;
            *reinterpret_cast<float4*>(&w_s[kk][c4*4]) =
                *reinterpret_cast<const float4*>(&g_fWt[(kc+kk)*Dd + c4*4]);
        }
        __syncthreads();

        #pragma unroll 4
        for (int kk=0; kk<32; kk++){
            float4 a0 = *reinterpret_cast<float4*>(&act_s[kk][ty*4]);
            float4 w0 = *reinterpret_cast<float4*>(&w_s[kk][tx*8]);
            float4 w1 = *reinterpret_cast<float4*>(&w_s[kk][tx*8+4]);
            float av[4] = {a0.x,a0.y,a0.z,a0.w};
            float wv[8] = {w0.x,w0.y,w0.z,w0.w,w1.x,w1.y,w1.z,w1.w};
            #pragma unroll
            for (int i=0;i<4;i++)
                #pragma unroll
                for (int j=0;j<8;j++) acc[i][j] = fmaf(av[i], wv[j], acc[i][j]);
        }
        __syncthreads();
    }

    float4 fb0 = *reinterpret_cast<const float4*>(&f_b[tx*8]);
    float4 fb1 = *reinterpret_cast<const float4*>(&f_b[tx*8+4]);
    float4 pw0 = *reinterpret_cast<const float4*>(&p_W[tx*8]);
    float4 pw1 = *reinterpret_cast<const float4*>(&p_W[tx*8+4]);
    float fbv[8] = {fb0.x,fb0.y,fb0.z,fb0.w,fb1.x,fb1.y,fb1.z,fb1.w};
    float pwv[8] = {pw0.x,pw0.y,pw0.z,pw0.w,pw1.x,pw1.y,pw1.z,pw1.w};

    float rs[4];
    #pragma unroll
    for (int i=0;i<4;i++){
        float s = 0.f;
        #pragma unroll
        for (int j=0;j<8;j++) s = fmaf(pwv[j], tanhf(acc[i][j] + fbv[j]), s);
        rs[i] = s;
    }
    #pragma unroll
    for (int o=1; o<16; o<<=1){
        #pragma unroll
        for (int i=0;i<4;i++) rs[i] += __shfl_xor_sync(0xffffffffu, rs[i], o);
    }
    if (tx == 0){
        float pb = p_b[0];
        #pragma unroll
        for (int i=0;i<4;i++) out_p[row0 + ty*4 + i] = sigmoidf_(rs[i] + pb);
    }
}

// ---------------- launch ----------------
extern "C" void kernel_launch(void* const* d_in, const int* in_sizes, int n_in,
                              void* d_out, int out_size)
{
    const int*   q       = (const int*)  d_in[0];
    const int*   r       = (const int*)  d_in[1];
    const int*   pid     = (const int*)  d_in[2];
    const float* pid_emb = (const float*)d_in[3];
    const float* k_emb   = (const float*)d_in[4];
    const float* v_emb   = (const float*)d_in[5];
    const float* Mk      = (const float*)d_in[6];
    const float* Mv0     = (const float*)d_in[7];
    const float* f_W     = (const float*)d_in[8];
    const float* f_b     = (const float*)d_in[9];
    const float* p_W     = (const float*)d_in[10];
    const float* p_b     = (const float*)d_in[11];
    const float* e_W     = (const float*)d_in[12];
    const float* e_b     = (const float*)d_in[13];
    const float* a_W     = (const float*)d_in[14];
    const float* a_b     = (const float*)d_in[15];

    float* out_p  = (float*)d_out;              // (64, 200)
    float* out_Mv = (float*)d_out + BT;         // (64, 201, 50, 128)

    k1_gather<<<BT/16, 256>>>(q, r, pid, pid_emb, k_emb, v_emb, Mk, e_W, a_W, f_W);
    {
        dim3 gea(BT/32, 2);
        k_ea_gemm<<<gea, 128>>>(e_b, a_b);
    }
    {
        dim3 g1(NC, Bb, 4);
        k2a_affine<<<g1, 256>>>();
        k2b_chunkstart<<<Bb, 256>>>(Mv0, out_Mv);
        dim3 g3(NC, Bb, 2);
        k2c_expand<<<g3, 256>>>(out_Mv);
    }
    k_f_gemm<<<BT/32, 128>>>(f_b, p_W, p_b, out_p);
}